// round 14
// baseline (speedup 1.0000x reference)
#include <cuda_runtime.h>
#include <cstdint>

// RandomPixelMapping: out[b,c,y,x] = table[b,c, clip(rint(x*255), 0, 255)]
// x: [64,3,512,512] f32, table: [64,3,256] f32, out: [64,3,512,512] f32.
//
// TERMINAL KERNEL — memory-controller roofline, reproduced 5x:
//   kernel 55.4-56.9us, 6.1-6.3 TB/s ncu; 7.28 TB/s app-level (91% of
//   8 TB/s HBM3e spec). Work is irreducible (403 MB single-pass stream).
// Design:
//  - bank-replicated LUT lut[idx][lane] (32 KB smem): lane l always reads
//    bank l -> provably conflict-free gather for any index distribution
//    (the single measured win: -2.2us vs scalar LUT)
//  - lane-rotated STS.128 fill (minimum-phase warp stores)
//  - 8-deep front-batched vec4 loads (MLP=8), CHUNKS=32 -> 6144 CTAs
//    (multi-wave oversubscription backfills per-CTA finish spread;
//     single-wave launch measured -6%, heavier amortization -2%)
//  - __float2int_rn = round-to-nearest-even, matching jnp.round exactly
// Falsified (neutral): MLP depth, .cs / evict_last+first policies,
// 256-bit ld/st.v8.b32, fill amortization, load-before-fill overlap.

#define PLANE_ELEMS    (512 * 512)          // 262144 elems per (b,c) plane
#define VEC_PER_PLANE  (PLANE_ELEMS / 4)    // 65536 float4
#define THREADS        256
#define CHUNKS         32                   // blocks per plane
#define VEC_PER_BLOCK  (VEC_PER_PLANE / CHUNKS)      // 2048 float4 per block
#define VEC_PER_THREAD (VEC_PER_BLOCK / THREADS)     // 8 float4 per thread

__global__ __launch_bounds__(THREADS)
void RandomPixelMapping_19593640805006_kernel(
    const float4* __restrict__ x,
    const float*  __restrict__ table,
    float4*       __restrict__ out)
{
    __shared__ float lut[256][32];

    const int tid   = threadIdx.x;
    const int lane  = tid & 31;
    const int plane = blockIdx.y;                 // 0..191  (b*3 + c)

    // Fill: thread tid owns LUT row tid; rotate the float4 column-group by
    // lane so each warp's STS.128 completes in the 4-phase minimum.
    {
        const float t = table[plane * 256 + tid];
        const float4 tv = make_float4(t, t, t, t);
        float4* row = reinterpret_cast<float4*>(lut[tid]);
#pragma unroll
        for (int j = 0; j < 8; ++j)
            row[(j + lane) & 7] = tv;
    }
    __syncthreads();

    const size_t base = (size_t)plane * VEC_PER_PLANE
                      + (size_t)blockIdx.x * VEC_PER_BLOCK
                      + tid;

    // Front-batch 8 independent vec4 loads (MLP=8), then conflict-free
    // gather and coalesced vec4 stores.
    float4 v[VEC_PER_THREAD];
#pragma unroll
    for (int j = 0; j < VEC_PER_THREAD; ++j)
        v[j] = x[base + (size_t)j * THREADS];

#pragma unroll
    for (int j = 0; j < VEC_PER_THREAD; ++j) {
        float4 r;
        int i0 = __float2int_rn(v[j].x * 255.0f);
        int i1 = __float2int_rn(v[j].y * 255.0f);
        int i2 = __float2int_rn(v[j].z * 255.0f);
        int i3 = __float2int_rn(v[j].w * 255.0f);
        i0 = min(max(i0, 0), 255);
        i1 = min(max(i1, 0), 255);
        i2 = min(max(i2, 0), 255);
        i3 = min(max(i3, 0), 255);
        r.x = lut[i0][lane];
        r.y = lut[i1][lane];
        r.z = lut[i2][lane];
        r.w = lut[i3][lane];
        out[base + (size_t)j * THREADS] = r;
    }
}

extern "C" void kernel_launch(void* const* d_in, const int* in_sizes, int n_in,
                              void* d_out, int out_size)
{
    const float4* x     = (const float4*)d_in[0];
    const float*  table = (const float*) d_in[1];
    float4*       out   = (float4*)d_out;

    dim3 grid(CHUNKS, 64 * 3);   // 32 chunks x 192 planes = 6144 CTAs
    RandomPixelMapping_19593640805006_kernel<<<grid, THREADS>>>(x, table, out);
}

// round 15
// speedup vs baseline: 1.0081x; 1.0081x over previous
#include <cuda_runtime.h>
#include <cstdint>

// RandomPixelMapping: out[b,c,y,x] = table[b,c, clip(rint(x*255), 0, 255)]
// x: [64,3,512,512] f32, table: [64,3,256] f32, out: [64,3,512,512] f32.
//
// TERMINAL KERNEL — memory-controller roofline, reproduced 6x:
//   kernel 55.4-56.9us, 6.1-6.3 TB/s ncu; 7.28 TB/s app-level (91% of
//   8 TB/s HBM3e spec). Work is irreducible (403 MB single-pass stream).
// Design:
//  - bank-replicated LUT lut[idx][lane] (32 KB smem): lane l always reads
//    bank l -> provably conflict-free gather for any index distribution
//    (the single measured win: -2.2us vs scalar LUT)
//  - lane-rotated STS.128 fill (minimum-phase warp stores)
//  - 8-deep front-batched vec4 loads (MLP=8), CHUNKS=32 -> 6144 CTAs
//    (multi-wave oversubscription backfills per-CTA finish spread;
//     single-wave launch measured -6%, heavier amortization -2%)
//  - __float2int_rn = round-to-nearest-even, matching jnp.round exactly
// Falsified (neutral): MLP depth, .cs / evict_last+first policies,
// 256-bit ld/st.v8.b32, fill amortization, load-before-fill overlap.

#define PLANE_ELEMS    (512 * 512)          // 262144 elems per (b,c) plane
#define VEC_PER_PLANE  (PLANE_ELEMS / 4)    // 65536 float4
#define THREADS        256
#define CHUNKS         32                   // blocks per plane
#define VEC_PER_BLOCK  (VEC_PER_PLANE / CHUNKS)      // 2048 float4 per block
#define VEC_PER_THREAD (VEC_PER_BLOCK / THREADS)     // 8 float4 per thread

__global__ __launch_bounds__(THREADS)
void RandomPixelMapping_19593640805006_kernel(
    const float4* __restrict__ x,
    const float*  __restrict__ table,
    float4*       __restrict__ out)
{
    __shared__ float lut[256][32];

    const int tid   = threadIdx.x;
    const int lane  = tid & 31;
    const int plane = blockIdx.y;                 // 0..191  (b*3 + c)

    // Fill: thread tid owns LUT row tid; rotate the float4 column-group by
    // lane so each warp's STS.128 completes in the 4-phase minimum.
    {
        const float t = table[plane * 256 + tid];
        const float4 tv = make_float4(t, t, t, t);
        float4* row = reinterpret_cast<float4*>(lut[tid]);
#pragma unroll
        for (int j = 0; j < 8; ++j)
            row[(j + lane) & 7] = tv;
    }
    __syncthreads();

    const size_t base = (size_t)plane * VEC_PER_PLANE
                      + (size_t)blockIdx.x * VEC_PER_BLOCK
                      + tid;

    // Front-batch 8 independent vec4 loads (MLP=8), then conflict-free
    // gather and coalesced vec4 stores.
    float4 v[VEC_PER_THREAD];
#pragma unroll
    for (int j = 0; j < VEC_PER_THREAD; ++j)
        v[j] = x[base + (size_t)j * THREADS];

#pragma unroll
    for (int j = 0; j < VEC_PER_THREAD; ++j) {
        float4 r;
        int i0 = __float2int_rn(v[j].x * 255.0f);
        int i1 = __float2int_rn(v[j].y * 255.0f);
        int i2 = __float2int_rn(v[j].z * 255.0f);
        int i3 = __float2int_rn(v[j].w * 255.0f);
        i0 = min(max(i0, 0), 255);
        i1 = min(max(i1, 0), 255);
        i2 = min(max(i2, 0), 255);
        i3 = min(max(i3, 0), 255);
        r.x = lut[i0][lane];
        r.y = lut[i1][lane];
        r.z = lut[i2][lane];
        r.w = lut[i3][lane];
        out[base + (size_t)j * THREADS] = r;
    }
}

extern "C" void kernel_launch(void* const* d_in, const int* in_sizes, int n_in,
                              void* d_out, int out_size)
{
    const float4* x     = (const float4*)d_in[0];
    const float*  table = (const float*) d_in[1];
    float4*       out   = (float4*)d_out;

    dim3 grid(CHUNKS, 64 * 3);   // 32 chunks x 192 planes = 6144 CTAs
    RandomPixelMapping_19593640805006_kernel<<<grid, THREADS>>>(x, table, out);
}